// round 17
// baseline (speedup 1.0000x reference)
#include <cuda_runtime.h>
#include <cuda_fp16.h>

// ---------------------------------------------------------------------------
// Hetero-GNN (5 hetero_conv layers) over N=100000 nodes.
// R17 = R16 (champion, 507.9us) + rank-trick CSR build:
//   count phase stores atomicAdd's return value as the edge's within-row
//   rank; fill becomes ATOMIC-FREE (col[rowptr[d]+rank[e]] = src[e]).
//   Launch order puts the big count kernel at ncu's capture slot.
// ---------------------------------------------------------------------------

#define N_NODES 100000
#define WPB 12                      // warps per block (node kernels)
#define NPB (WPB * 4)               // nodes per block

__device__ float g_h  [N_NODES * 32];
__device__ float g_h2 [N_NODES * 32];
__device__ float g_x8 [N_NODES * 8];

__device__ int g_deg_t[N_NODES];
__device__ int g_deg_i[N_NODES];
__device__ int g_rpt  [N_NODES + 1];
__device__ int g_rpi  [N_NODES + 1];
__device__ int g_bsum_t[1024];
__device__ int g_bsum_i[1024];
__device__ int g_rank_t[100000];
__device__ int g_rank_i[3200000];
__device__ int g_col_t[100000];
__device__ int g_col_i[3200000];

// ---------------------------------------------------------------------------
// CSR build (rank trick: count returns rank, fill is atomic-free)
// ---------------------------------------------------------------------------
__global__ void zero2_kernel(int* __restrict__ a, int* __restrict__ b, int n) {
    int i = blockIdx.x * blockDim.x + threadIdx.x;
    if (i < n) { a[i] = 0; b[i] = 0; }
}

__global__ void count_rank(const int* __restrict__ dst, int E,
                           int* __restrict__ deg, int* __restrict__ rank) {
    int i = blockIdx.x * blockDim.x + threadIdx.x;
    if (i < E) rank[i] = atomicAdd(&deg[dst[i]], 1);
}

__global__ void scan_p1(const int* __restrict__ deg, int* __restrict__ rowptr,
                        int* __restrict__ bsum, int n) {
    __shared__ int sh[1024];
    int i = blockIdx.x * 1024 + threadIdx.x;
    int v = (i < n) ? deg[i] : 0;
    sh[threadIdx.x] = v;
    __syncthreads();
    for (int off = 1; off < 1024; off <<= 1) {
        int t = (threadIdx.x >= off) ? sh[threadIdx.x - off] : 0;
        __syncthreads();
        sh[threadIdx.x] += t;
        __syncthreads();
    }
    if (i < n) rowptr[i] = sh[threadIdx.x] - v;
    if (threadIdx.x == 1023) bsum[blockIdx.x] = sh[1023];
}

__global__ void scan_p2(int* __restrict__ bsum, int nb) {
    __shared__ int sh[1024];
    int v = (threadIdx.x < nb) ? bsum[threadIdx.x] : 0;
    sh[threadIdx.x] = v;
    __syncthreads();
    for (int off = 1; off < 1024; off <<= 1) {
        int t = (threadIdx.x >= off) ? sh[threadIdx.x - off] : 0;
        __syncthreads();
        sh[threadIdx.x] += t;
        __syncthreads();
    }
    if (threadIdx.x < nb) bsum[threadIdx.x] = sh[threadIdx.x] - v;
}

__global__ void scan_p3(int* __restrict__ rowptr, const int* __restrict__ bsum,
                        int n, int E) {
    int i = blockIdx.x * blockDim.x + threadIdx.x;
    if (i < n) rowptr[i] = rowptr[i] + bsum[i >> 10];
    if (i == 0) rowptr[n] = E;
}

// Atomic-free fill: position = rowptr[dst] + rank (rank from count phase).
__global__ void fill_rank(const int* __restrict__ src, const int* __restrict__ dst,
                          const int* __restrict__ rank, int E,
                          const int* __restrict__ rowptr, int* __restrict__ col) {
    int i = blockIdx.x * blockDim.x + threadIdx.x;
    if (i < E) {
        int d = dst[i];
        col[rowptr[d] + rank[i]] = src[i];
    }
}

__global__ void repack_x8(const float* __restrict__ x, float* __restrict__ x8, int n) {
    int i = blockIdx.x * blockDim.x + threadIdx.x;
    if (i < n * 8) {
        int node = i >> 3, c = i & 7;
        x8[i] = (c < 6) ? x[node * 6 + c] : 0.f;
    }
}

// ---------------------------------------------------------------------------
// Fused HIDDEN layer (32->32, residual). WPB warps x 4 nodes.
// ---------------------------------------------------------------------------
__global__ void __launch_bounds__(WPB * 32)
fused_hidden2(const float* __restrict__ h,
              const int* __restrict__ rpt, const int* __restrict__ colt,
              const int* __restrict__ rpi, const int* __restrict__ coli,
              const float* __restrict__ Wt, const float* __restrict__ Wi,
              const float* __restrict__ Wr, const float* __restrict__ b,
              float* __restrict__ hout, int n) {
    __shared__ float4 sW4[32 * 32];          // 16 KB
    __shared__ float4 sV[WPB * 4 * 32];      // 24 KB
    __shared__ float  sB[32];

    for (int i = threadIdx.x; i < 32 * 32; i += blockDim.x) {
        int ci = i >> 5, l = i & 31;
        sW4[i] = make_float4(Wt[ci * 32 + l], Wi[ci * 32 + l], Wr[ci * 32 + l], 0.f);
    }
    if (threadIdx.x < 32) sB[threadIdx.x] = b[threadIdx.x];
    __syncthreads();

    int warp = threadIdx.x >> 5, lane = threadIdx.x & 31;
    int node0 = (blockIdx.x * WPB + warp) * 4;
    if (node0 >= n) return;
    int g = lane >> 3, c = lane & 7;
    const float4* h4 = (const float4*)h;
    float4* vbase = &sV[warp * 128];

#pragma unroll
    for (int j = 0; j < 4; j++) {
        int node = node0 + j;
        if (node >= n) break;

        float4 aT = make_float4(0.f, 0.f, 0.f, 0.f);
        float4 aM = make_float4(0.f, 0.f, 0.f, 0.f);

        int b0 = rpt[node], e0 = rpt[node + 1];
        for (int e = b0; e < e0; e += 4) {
            int ei = e + g;
            int ec = (ei < e0) ? ei : (e0 - 1);
            int s = colt[ec];
            float4 v = h4[s * 8 + c];
            if (ei < e0) { aT.x += v.x; aT.y += v.y; aT.z += v.z; aT.w += v.w; }
        }

        int b1 = rpi[node], e1 = rpi[node + 1];
        for (int e = b1; e < e1; e += 4) {
            int ei = e + g;
            int ec = (ei < e1) ? ei : (e1 - 1);
            int s = coli[ec];
            float4 v = h4[s * 8 + c];
            if (ei < e1) { aM.x += v.x; aM.y += v.y; aM.z += v.z; aM.w += v.w; }
        }

#pragma unroll
        for (int off = 8; off <= 16; off <<= 1) {
            aT.x += __shfl_xor_sync(0xffffffffu, aT.x, off);
            aT.y += __shfl_xor_sync(0xffffffffu, aT.y, off);
            aT.z += __shfl_xor_sync(0xffffffffu, aT.z, off);
            aT.w += __shfl_xor_sync(0xffffffffu, aT.w, off);
            aM.x += __shfl_xor_sync(0xffffffffu, aM.x, off);
            aM.y += __shfl_xor_sync(0xffffffffu, aM.y, off);
            aM.z += __shfl_xor_sync(0xffffffffu, aM.z, off);
            aM.w += __shfl_xor_sync(0xffffffffu, aM.w, off);
        }
        float invd = 1.0f / fmaxf((float)(e1 - b1), 1.0f);
        aM.x *= invd; aM.y *= invd; aM.z *= invd; aM.w *= invd;

        if (lane < 8) {
            float4 hv = h4[node * 8 + lane];
            vbase[j * 32 + lane * 4 + 0] = make_float4(aT.x, aM.x, hv.x, 0.f);
            vbase[j * 32 + lane * 4 + 1] = make_float4(aT.y, aM.y, hv.y, 0.f);
            vbase[j * 32 + lane * 4 + 2] = make_float4(aT.z, aM.z, hv.z, 0.f);
            vbase[j * 32 + lane * 4 + 3] = make_float4(aT.w, aM.w, hv.w, 0.f);
        }
    }
    __syncwarp();

    float acc0 = sB[lane], acc1 = sB[lane], acc2 = sB[lane], acc3 = sB[lane];
#pragma unroll
    for (int ci = 0; ci < 32; ci++) {
        float4 w = sW4[ci * 32 + lane];
        float4 v0 = vbase[0 * 32 + ci];
        float4 v1 = vbase[1 * 32 + ci];
        float4 v2 = vbase[2 * 32 + ci];
        float4 v3 = vbase[3 * 32 + ci];
        acc0 += v0.x * w.x + v0.y * w.y + v0.z * w.z;
        acc1 += v1.x * w.x + v1.y * w.y + v1.z * w.z;
        acc2 += v2.x * w.x + v2.y * w.y + v2.z * w.z;
        acc3 += v3.x * w.x + v3.y * w.y + v3.z * w.z;
    }
    float accs[4] = {acc0, acc1, acc2, acc3};
#pragma unroll
    for (int j = 0; j < 4; j++) {
        int node = node0 + j;
        if (node < n) {
            float hv = vbase[j * 32 + lane].z;
            hout[node * 32 + lane] = fmaxf(accs[j], 0.f) + hv;
        }
    }
}

// ---------------------------------------------------------------------------
// Fused HEAD layer (6->32). Padded x8 rows; 16 edge-groups x 2 lanes.
// ---------------------------------------------------------------------------
__global__ void __launch_bounds__(WPB * 32)
fused_head2(const float* __restrict__ x8,
            const int* __restrict__ rpt, const int* __restrict__ colt,
            const int* __restrict__ rpi, const int* __restrict__ coli,
            const float* __restrict__ Wt, const float* __restrict__ Wi,
            const float* __restrict__ Wr, const float* __restrict__ b,
            float* __restrict__ hout, int n) {
    __shared__ float4 sW4[6 * 32];
    __shared__ float4 sV[WPB * 4 * 8];
    __shared__ float  sB[32];

    for (int i = threadIdx.x; i < 6 * 32; i += blockDim.x) {
        int ci = i >> 5, l = i & 31;
        sW4[i] = make_float4(Wt[ci * 32 + l], Wi[ci * 32 + l], Wr[ci * 32 + l], 0.f);
    }
    if (threadIdx.x < 32) sB[threadIdx.x] = b[threadIdx.x];
    __syncthreads();

    int warp = threadIdx.x >> 5, lane = threadIdx.x & 31;
    int node0 = (blockIdx.x * WPB + warp) * 4;
    if (node0 >= n) return;
    int g = lane >> 1, c = lane & 1;
    const float4* x4 = (const float4*)x8;
    float4* vbase = &sV[warp * 32];

#pragma unroll
    for (int j = 0; j < 4; j++) {
        int node = node0 + j;
        if (node >= n) break;

        float4 aT = make_float4(0.f, 0.f, 0.f, 0.f);
        float4 aM = make_float4(0.f, 0.f, 0.f, 0.f);

        int b0 = rpt[node], e0 = rpt[node + 1];
        for (int e = b0; e < e0; e += 16) {
            int ei = e + g;
            int ec = (ei < e0) ? ei : (e0 - 1);
            int s = colt[ec];
            float4 v = x4[s * 2 + c];
            if (ei < e0) { aT.x += v.x; aT.y += v.y; aT.z += v.z; aT.w += v.w; }
        }

        int b1 = rpi[node], e1 = rpi[node + 1];
        for (int e = b1; e < e1; e += 16) {
            int ei = e + g;
            int ec = (ei < e1) ? ei : (e1 - 1);
            int s = coli[ec];
            float4 v = x4[s * 2 + c];
            if (ei < e1) { aM.x += v.x; aM.y += v.y; aM.z += v.z; aM.w += v.w; }
        }

#pragma unroll
        for (int off = 2; off <= 16; off <<= 1) {
            aT.x += __shfl_xor_sync(0xffffffffu, aT.x, off);
            aT.y += __shfl_xor_sync(0xffffffffu, aT.y, off);
            aT.z += __shfl_xor_sync(0xffffffffu, aT.z, off);
            aT.w += __shfl_xor_sync(0xffffffffu, aT.w, off);
            aM.x += __shfl_xor_sync(0xffffffffu, aM.x, off);
            aM.y += __shfl_xor_sync(0xffffffffu, aM.y, off);
            aM.z += __shfl_xor_sync(0xffffffffu, aM.z, off);
            aM.w += __shfl_xor_sync(0xffffffffu, aM.w, off);
        }
        float invd = 1.0f / fmaxf((float)(e1 - b1), 1.0f);
        aM.x *= invd; aM.y *= invd; aM.z *= invd; aM.w *= invd;

        if (lane < 2) {
            float4 xv = x4[node * 2 + lane];
            vbase[j * 8 + lane * 4 + 0] = make_float4(aT.x, aM.x, xv.x, 0.f);
            vbase[j * 8 + lane * 4 + 1] = make_float4(aT.y, aM.y, xv.y, 0.f);
            vbase[j * 8 + lane * 4 + 2] = make_float4(aT.z, aM.z, xv.z, 0.f);
            vbase[j * 8 + lane * 4 + 3] = make_float4(aT.w, aM.w, xv.w, 0.f);
        }
    }
    __syncwarp();

    float acc0 = sB[lane], acc1 = sB[lane], acc2 = sB[lane], acc3 = sB[lane];
#pragma unroll
    for (int ci = 0; ci < 6; ci++) {
        float4 w = sW4[ci * 32 + lane];
        float4 v0 = vbase[0 * 8 + ci];
        float4 v1 = vbase[1 * 8 + ci];
        float4 v2 = vbase[2 * 8 + ci];
        float4 v3 = vbase[3 * 8 + ci];
        acc0 += v0.x * w.x + v0.y * w.y + v0.z * w.z;
        acc1 += v1.x * w.x + v1.y * w.y + v1.z * w.z;
        acc2 += v2.x * w.x + v2.y * w.y + v2.z * w.z;
        acc3 += v3.x * w.x + v3.y * w.y + v3.z * w.z;
    }
    float accs[4] = {acc0, acc1, acc2, acc3};
#pragma unroll
    for (int j = 0; j < 4; j++) {
        int node = node0 + j;
        if (node < n) hout[node * 32 + lane] = fmaxf(accs[j], 0.f);
    }
}

// ---------------------------------------------------------------------------
// Fused LAST layer (32->64 + projection residual). WPB warps x 4 nodes.
// ---------------------------------------------------------------------------
__global__ void __launch_bounds__(WPB * 32)
fused_last2(const float* __restrict__ h,
            const int* __restrict__ rpt, const int* __restrict__ colt,
            const int* __restrict__ rpi, const int* __restrict__ coli,
            const float* __restrict__ Wt, const float* __restrict__ Wi,
            const float* __restrict__ Wr, const float* __restrict__ b,
            const float* __restrict__ Wp,
            float* __restrict__ out, int n) {
    __shared__ float4 sW4a[32 * 32];         // 16 KB
    __shared__ float4 sW4b[32 * 32];         // 16 KB
    __shared__ float4 sV[WPB * 4 * 32];      // 24 KB

    for (int i = threadIdx.x; i < 32 * 32; i += blockDim.x) {
        int ci = i >> 5, l = i & 31;
        sW4a[i] = make_float4(Wt[ci * 64 + l],      Wi[ci * 64 + l],      Wr[ci * 64 + l],      Wp[ci * 64 + l]);
        sW4b[i] = make_float4(Wt[ci * 64 + l + 32], Wi[ci * 64 + l + 32], Wr[ci * 64 + l + 32], Wp[ci * 64 + l + 32]);
    }
    __syncthreads();

    int warp = threadIdx.x >> 5, lane = threadIdx.x & 31;
    int node0 = (blockIdx.x * WPB + warp) * 4;
    if (node0 >= n) return;
    int g = lane >> 3, c = lane & 7;
    const float4* h4 = (const float4*)h;
    float4* vbase = &sV[warp * 128];

    float bias0 = b[lane], bias1 = b[lane + 32];

#pragma unroll
    for (int j = 0; j < 4; j++) {
        int node = node0 + j;
        if (node >= n) break;

        float4 aT = make_float4(0.f, 0.f, 0.f, 0.f);
        float4 aM = make_float4(0.f, 0.f, 0.f, 0.f);

        int b0 = rpt[node], e0 = rpt[node + 1];
        for (int e = b0; e < e0; e += 4) {
            int ei = e + g;
            int ec = (ei < e0) ? ei : (e0 - 1);
            int s = colt[ec];
            float4 v = h4[s * 8 + c];
            if (ei < e0) { aT.x += v.x; aT.y += v.y; aT.z += v.z; aT.w += v.w; }
        }

        int b1 = rpi[node], e1 = rpi[node + 1];
        for (int e = b1; e < e1; e += 4) {
            int ei = e + g;
            int ec = (ei < e1) ? ei : (e1 - 1);
            int s = coli[ec];
            float4 v = h4[s * 8 + c];
            if (ei < e1) { aM.x += v.x; aM.y += v.y; aM.z += v.z; aM.w += v.w; }
        }

#pragma unroll
        for (int off = 8; off <= 16; off <<= 1) {
            aT.x += __shfl_xor_sync(0xffffffffu, aT.x, off);
            aT.y += __shfl_xor_sync(0xffffffffu, aT.y, off);
            aT.z += __shfl_xor_sync(0xffffffffu, aT.z, off);
            aT.w += __shfl_xor_sync(0xffffffffu, aT.w, off);
            aM.x += __shfl_xor_sync(0xffffffffu, aM.x, off);
            aM.y += __shfl_xor_sync(0xffffffffu, aM.y, off);
            aM.z += __shfl_xor_sync(0xffffffffu, aM.z, off);
            aM.w += __shfl_xor_sync(0xffffffffu, aM.w, off);
        }
        float invd = 1.0f / fmaxf((float)(e1 - b1), 1.0f);
        aM.x *= invd; aM.y *= invd; aM.z *= invd; aM.w *= invd;

        if (lane < 8) {
            float4 hv = h4[node * 8 + lane];
            vbase[j * 32 + lane * 4 + 0] = make_float4(aT.x, aM.x, hv.x, 0.f);
            vbase[j * 32 + lane * 4 + 1] = make_float4(aT.y, aM.y, hv.y, 0.f);
            vbase[j * 32 + lane * 4 + 2] = make_float4(aT.z, aM.z, hv.z, 0.f);
            vbase[j * 32 + lane * 4 + 3] = make_float4(aT.w, aM.w, hv.w, 0.f);
        }
    }
    __syncwarp();

    float a0[4], a1[4], p0[4], p1[4];
#pragma unroll
    for (int j = 0; j < 4; j++) { a0[j] = bias0; a1[j] = bias1; p0[j] = 0.f; p1[j] = 0.f; }

#pragma unroll
    for (int ci = 0; ci < 32; ci++) {
        float4 wa = sW4a[ci * 32 + lane];
        float4 wb = sW4b[ci * 32 + lane];
#pragma unroll
        for (int j = 0; j < 4; j++) {
            float4 v = vbase[j * 32 + ci];
            a0[j] += v.x * wa.x + v.y * wa.y + v.z * wa.z;
            p0[j] += v.z * wa.w;
            a1[j] += v.x * wb.x + v.y * wb.y + v.z * wb.z;
            p1[j] += v.z * wb.w;
        }
    }
#pragma unroll
    for (int j = 0; j < 4; j++) {
        int node = node0 + j;
        if (node < n) {
            out[node * 64 + lane]      = fmaxf(a0[j], 0.f) + p0[j];
            out[node * 64 + lane + 32] = fmaxf(a1[j], 0.f) + p1[j];
        }
    }
}

// ---------------------------------------------------------------------------
// Launch
// ---------------------------------------------------------------------------
extern "C" void kernel_launch(void* const* d_in, const int* in_sizes, int n_in,
                              void* d_out, int out_size) {
    const float* x        = (const float*)d_in[0];
    const int*   ei_t     = (const int*)d_in[1];
    const int*   ei_i     = (const int*)d_in[2];
    const float* head_Wt  = (const float*)d_in[3];
    const float* head_Wi  = (const float*)d_in[4];
    const float* head_Wr  = (const float*)d_in[5];
    const float* head_b   = (const float*)d_in[6];
    const float* blk_Wt   = (const float*)d_in[7];
    const float* blk_Wi   = (const float*)d_in[8];
    const float* blk_Wr   = (const float*)d_in[9];
    const float* blk_b    = (const float*)d_in[10];
    const float* last_Wt  = (const float*)d_in[11];
    const float* last_Wi  = (const float*)d_in[12];
    const float* last_Wr  = (const float*)d_in[13];
    const float* last_b   = (const float*)d_in[14];
    const float* last_proj= (const float*)d_in[15];

    const int n  = in_sizes[0] / 6;      // 100000
    const int Et = in_sizes[1] / 2;      // 100000
    const int Ei = in_sizes[2] / 2;      // 3200000

    float *h, *h2, *x8;
    int *degt, *degi, *rpt, *rpi, *colt, *coli, *bst, *bsi, *rkt, *rki;
    cudaGetSymbolAddress((void**)&h,    g_h);
    cudaGetSymbolAddress((void**)&h2,   g_h2);
    cudaGetSymbolAddress((void**)&x8,   g_x8);
    cudaGetSymbolAddress((void**)&degt, g_deg_t);
    cudaGetSymbolAddress((void**)&degi, g_deg_i);
    cudaGetSymbolAddress((void**)&rpt,  g_rpt);
    cudaGetSymbolAddress((void**)&rpi,  g_rpi);
    cudaGetSymbolAddress((void**)&bst,  g_bsum_t);
    cudaGetSymbolAddress((void**)&bsi,  g_bsum_i);
    cudaGetSymbolAddress((void**)&rkt,  g_rank_t);
    cudaGetSymbolAddress((void**)&rki,  g_rank_i);
    cudaGetSymbolAddress((void**)&colt, g_col_t);
    cudaGetSymbolAddress((void**)&coli, g_col_i);

    const int T = 256;
    const int TB = WPB * 32;           // 384
    int nb = (n + 1023) / 1024;
    int nodeBlocks = (n + NPB - 1) / NPB;

    // --- CSR build (rank trick). Launch 3 = count_rank(inter) for ncu. ---
    zero2_kernel<<<(n + T - 1) / T, T>>>(degt, degi, n);
    count_rank<<<(Et + T - 1) / T, T>>>(ei_t + Et, Et, degt, rkt);
    repack_x8<<<(n * 8 + T - 1) / T, T>>>(x, x8, n);
    count_rank<<<(Ei + T - 1) / T, T>>>(ei_i + Ei, Ei, degi, rki);   // ncu slot

    scan_p1<<<nb, 1024>>>(degt, rpt, bst, n);
    scan_p1<<<nb, 1024>>>(degi, rpi, bsi, n);
    scan_p2<<<1, 1024>>>(bst, nb);
    scan_p2<<<1, 1024>>>(bsi, nb);
    scan_p3<<<(n + T) / T, T>>>(rpt, bst, n, Et);
    scan_p3<<<(n + T) / T, T>>>(rpi, bsi, n, Ei);

    fill_rank<<<(Et + T - 1) / T, T>>>(ei_t, ei_t + Et, rkt, Et, rpt, colt);
    fill_rank<<<(Ei + T - 1) / T, T>>>(ei_i, ei_i + Ei, rki, Ei, rpi, coli);

    // --- head: 6 -> 32 ---
    fused_head2<<<nodeBlocks, TB>>>(x8, rpt, colt, rpi, coli,
                                    head_Wt, head_Wi, head_Wr, head_b, h, n);

    // --- 3 residual blocks: 32 -> 32 ---
    for (int i = 0; i < 3; i++) {
        fused_hidden2<<<nodeBlocks, TB>>>(h, rpt, colt, rpi, coli,
                                          blk_Wt + i * 32 * 32, blk_Wi + i * 32 * 32,
                                          blk_Wr + i * 32 * 32, blk_b + i * 32,
                                          h2, n);
        float* tmp = h; h = h2; h2 = tmp;
    }

    // --- last: 32 -> 64 ---
    fused_last2<<<nodeBlocks, TB>>>(h, rpt, colt, rpi, coli,
                                    last_Wt, last_Wi, last_Wr, last_b, last_proj,
                                    (float*)d_out, n);
}